// round 6
// baseline (speedup 1.0000x reference)
#include <cuda_runtime.h>
#include <cstdint>

#define NCH    30           // channels per cell
#define WTILE  16           // cells per warp-stage
#define THR    128          // 4 warps per CTA
#define SCELL  49
#define GRID   1036         // 7 CTAs/SM on 148 SMs
#define NW     (GRID * 4)   // total independent warp pipelines = 4144
#define WSTG_F (WTILE * NCH * 2)   // floats per warp stage = 960 (3840 B)

__device__ float g_partials[2048];
__device__ unsigned int g_count;   // zeroed at load; reset by last CTA

__device__ __forceinline__ void cp16(uint32_t saddr, const void* gptr) {
    asm volatile("cp.async.cg.shared.global [%0], [%1], 16;"
                 :: "r"(saddr), "l"(gptr) : "memory");
}

// warp-private stage: 240 float4 (120 pred + 120 target), own commit group
__device__ __forceinline__ void issue_wtile(uint32_t sbase, const float4* p4,
                                            const float4* t4, int T, int lane) {
    const float4* gp = p4 + (size_t)T * 120;
    const float4* gt = t4 + (size_t)T * 120;
    #pragma unroll
    for (int r = 0; r < 8; ++r) {
        int i = lane + r * 32;
        if (i < 240) {
            if (i < 120) cp16(sbase + i * 16, gp + i);
            else         cp16(sbase + 1920 + (i - 120) * 16, gt + (i - 120));
        }
    }
    asm volatile("cp.async.commit_group;" ::: "memory");
}

__global__ void __launch_bounds__(THR) yolo_loss_warp(
    const float* __restrict__ pred, const float* __restrict__ target,
    int ntilesW, float invN, float* __restrict__ out)
{
    __shared__ float buf[4 * 2 * WSTG_F];   // 30720 B: [warp][stage][960]
    __shared__ float warpsum[4];
    __shared__ unsigned int s_rank;

    const int tid  = threadIdx.x;
    const int wid  = tid >> 5;
    const int lane = tid & 31;
    const float4* p4 = (const float4*)pred;
    const float4* t4 = (const float4*)target;
    const float STEP = 1.0f / 7.0f;

    const uint32_t wbase = (uint32_t)__cvta_generic_to_shared(buf)
                         + wid * (2 * WSTG_F * 4);
    const int gw = blockIdx.x * 4 + wid;           // global warp id
    const int my_n = (gw < ntilesW) ? (ntilesW - gw + NW - 1) / NW : 0;

    float acc = 0.0f;                              // per-lane accumulator

    if (my_n > 0)
        issue_wtile(wbase, p4, t4, gw, lane);      // prologue -> stage 0

    for (int it = 0; it < my_n; ++it) {
        const int T = gw + it * NW;
        if (it + 1 < my_n) {
            issue_wtile(wbase + ((it + 1) & 1) * (WSTG_F * 4), p4, t4,
                        T + NW, lane);
            asm volatile("cp.async.wait_group 1;" ::: "memory");
        } else {
            asm volatile("cp.async.wait_group 0;" ::: "memory");
        }
        __syncwarp();                              // publish stage within warp

        const float* S  = buf + wid * (2 * WSTG_F) + (it & 1) * WSTG_F;
        const int    c  = (lane < WTILE) ? lane : lane - WTILE;
        const float* P  = S + c * NCH;
        const float* Tc = S + WTILE * NCH + c * NCH;
        const int cell  = T * WTILE + c;
        const int c49   = cell % SCELL;

        if (lane < WTILE) {
            // ---- lanes 0-15: box / conf / IoU for cell c ----
            const float gy = (float)(c49 / 7);
            const float gx = (float)(c49 % 7);
            const float mask = (Tc[9] > 0.0f) ? 1.0f : 0.0f;

            float iou[2];
            #pragma unroll
            for (int b = 0; b < 2; ++b) {
                const float* pb = P + 5 * b;
                const float* tb = Tc + 5 * b;
                float pw = fmaxf(pb[2], 0.0f), ph = fmaxf(pb[3], 0.0f);
                float px = fmaxf((pb[0] + gx) * STEP - pb[2] * 0.5f, 0.0f);
                float py = fmaxf((pb[1] + gy) * STEP - pb[3] * 0.5f, 0.0f);
                float tw = fmaxf(tb[2], 0.0f), th = fmaxf(tb[3], 0.0f);
                float tx = fmaxf((tb[0] + gx) * STEP - tb[2] * 0.5f, 0.0f);
                float ty = fmaxf((tb[1] + gy) * STEP - tb[3] * 0.5f, 0.0f);
                float iw = fmaxf(pw + tw - (fmaxf(px + pw, tx + tw) - fminf(px, tx)), 0.0f);
                float ih = fmaxf(ph + th - (fmaxf(py + ph, ty + th) - fminf(py, ty)), 0.0f);
                float inter = iw * ih;
                float uni = pw * ph + tw * th - inter;
                iou[b] = inter / (uni + 1e-10f);
            }
            const int resp = (iou[1] > iou[0]) ? 1 : 0;

            #pragma unroll
            for (int b = 0; b < 2; ++b) {
                const float ob = (b == resp) ? mask : 0.0f;
                const float* pb = P + 5 * b;
                const float* tb = Tc + 5 * b;
                float d0 = pb[0] - tb[0], d1 = pb[1] - tb[1];
                float d2 = pb[2] - tb[2], d3 = pb[3] - tb[3];
                acc += 5.0f * ob * (d0 * d0 + d1 * d1 + d2 * d2 + d3 * d3);
                float cf = pb[4];
                float dc = cf - iou[b];
                acc += ob * dc * dc + 0.5f * (1.0f - ob) * cf * cf;
            }
        } else {
            // ---- lanes 16-31: class loss for cell c ----
            const float mask = (Tc[9] > 0.0f) ? 1.0f : 0.0f;
            float cls = 0.0f;
            #pragma unroll
            for (int k = 10; k < 30; ++k) {
                float d = P[k] - Tc[k];
                cls += d * d;
            }
            acc += mask * cls;
        }
        __syncwarp();                              // guard stage reuse
    }

    // ---- one reduction at the very end ----
    #pragma unroll
    for (int o = 16; o; o >>= 1)
        acc += __shfl_down_sync(0xffffffffu, acc, o);
    if (lane == 0) warpsum[wid] = acc;
    __syncthreads();

    if (tid == 0) {
        float s = (warpsum[0] + warpsum[1]) + (warpsum[2] + warpsum[3]);
        __stcg(&g_partials[blockIdx.x], s);
        unsigned int rank;
        asm volatile("atom.acq_rel.gpu.global.add.u32 %0, [%1], %2;"
                     : "=r"(rank) : "l"(&g_count), "r"(1u) : "memory");
        s_rank = rank;
    }
    __syncthreads();

    // ---- last CTA folds all partials in fixed order ----
    if (s_rank == GRID - 1) {
        float s = 0.0f;
        for (int i = tid; i < GRID; i += THR)
            s += __ldcg(&g_partials[i]);
        #pragma unroll
        for (int o = 16; o; o >>= 1)
            s += __shfl_down_sync(0xffffffffu, s, o);
        __shared__ float fin[THR / 32];
        if (lane == 0) fin[wid] = s;
        __syncthreads();
        if (tid == 0) {
            float tot = (fin[0] + fin[1]) + (fin[2] + fin[3]);
            out[0] = tot * invN;
            g_count = 0;                           // reset for graph replay
        }
    }
}

extern "C" void kernel_launch(void* const* d_in, const int* in_sizes, int n_in,
                              void* d_out, int out_size)
{
    const float* pred   = (const float*)d_in[0];
    const float* target = (const float*)d_in[1];
    const int total   = in_sizes[0];          // N*49*30
    const int ncells  = total / NCH;          // 802816
    const int ntilesW = ncells / WTILE;       // 50176 (exact)
    const float invN  = 1.0f / (float)(ncells / SCELL);

    yolo_loss_warp<<<GRID, THR>>>(pred, target, ntilesW, invN, (float*)d_out);
}

// round 7
// speedup vs baseline: 1.1006x; 1.1006x over previous
#include <cuda_runtime.h>
#include <cstdint>

#define NCH   30            // channels per cell
#define TILE  64            // cells per pipeline stage
#define THR   128           // threads per CTA
#define SCELL 49
#define STAGE_F (TILE * NCH * 2)   // floats per stage (pred+target) = 3840
#define GRID  1036          // 7 CTAs/SM on 148 SMs (smem-limited max)

__device__ float g_partials[2048];
__device__ unsigned int g_count;    // zeroed at load; reset by last CTA

__device__ __forceinline__ void cp16(uint32_t saddr, const void* gptr) {
    asm volatile("cp.async.cg.shared.global [%0], [%1], 16;"
                 :: "r"(saddr), "l"(gptr) : "memory");
}

// stage a full tile (960 float4: 480 pred + 480 target) cooperatively
__device__ __forceinline__ void issue_tile(uint32_t sbase, const float4* p4,
                                           const float4* t4, int tile, int tid) {
    const float4* gp = p4 + (size_t)tile * 480;
    const float4* gt = t4 + (size_t)tile * 480;
    #pragma unroll
    for (int k = 0; k < 8; ++k) {
        int i = tid + k * THR;
        if (i < 960) {
            if (i < 480) cp16(sbase + i * 16, gp + i);
            else         cp16(sbase + 480 * 16 + (i - 480) * 16, gt + (i - 480));
        }
    }
    asm volatile("cp.async.commit_group;" ::: "memory");
}

__global__ void __launch_bounds__(THR) yolo_loss_pipe(
    const float* __restrict__ pred, const float* __restrict__ target,
    int ntiles, float invN, float* __restrict__ out)
{
    __shared__ float buf[2 * STAGE_F];        // 30720 B -> 7 CTAs/SM
    __shared__ float warpsum[4];
    __shared__ unsigned int s_rank;

    const int tid = threadIdx.x;
    const uint32_t sm0 = (uint32_t)__cvta_generic_to_shared(buf);
    const float4* p4 = (const float4*)pred;
    const float4* t4 = (const float4*)target;

    const int bx = blockIdx.x;
    const int my_n = (bx < ntiles) ? (ntiles - bx + GRID - 1) / GRID : 0;
    const float STEP = 1.0f / 7.0f;
    float acc = 0.0f;                          // per-THREAD accumulator

    if (my_n > 0)
        issue_tile(sm0, p4, t4, bx, tid);      // prologue -> stage 0

    for (int it = 0; it < my_n; ++it) {
        const int tile = bx + it * GRID;
        const bool has_next = (it + 1 < my_n);
        if (has_next)
            asm volatile("cp.async.wait_group 0;" ::: "memory");   // stage it ready
        else
            asm volatile("cp.async.wait_group 0;" ::: "memory");
        // NOTE: with depth-2 and issue-after-sync, at this point only the
        // current stage's group can be outstanding -> wait 0 is exact.
        __syncthreads();                       // everyone done with stage it-1

        if (has_next)                          // refill the stage just freed
            issue_tile(sm0 + ((it + 1) & 1) * (STAGE_F * 4), p4, t4,
                       tile + GRID, tid);

        const float* S = buf + (it & 1) * STAGE_F;

        if (tid < TILE) {
            // ---- warps 0-1: box/conf/IoU losses for cell tid ----
            const float* P = S + tid * NCH;
            const float* T = S + TILE * NCH + tid * NCH;
            const int cell = tile * TILE + tid;
            const int c49 = cell % SCELL;
            const float gy = (float)(c49 / 7);
            const float gx = (float)(c49 % 7);
            const float mask = (T[9] > 0.0f) ? 1.0f : 0.0f;

            float iou[2];
            #pragma unroll
            for (int b = 0; b < 2; ++b) {
                const float* pb = P + 5 * b;
                const float* tb = T + 5 * b;
                float pw = fmaxf(pb[2], 0.0f), ph = fmaxf(pb[3], 0.0f);
                float px = fmaxf((pb[0] + gx) * STEP - pb[2] * 0.5f, 0.0f);
                float py = fmaxf((pb[1] + gy) * STEP - pb[3] * 0.5f, 0.0f);
                float tw = fmaxf(tb[2], 0.0f), th = fmaxf(tb[3], 0.0f);
                float tx = fmaxf((tb[0] + gx) * STEP - tb[2] * 0.5f, 0.0f);
                float ty = fmaxf((tb[1] + gy) * STEP - tb[3] * 0.5f, 0.0f);
                float iw = fmaxf(pw + tw - (fmaxf(px + pw, tx + tw) - fminf(px, tx)), 0.0f);
                float ih = fmaxf(ph + th - (fmaxf(py + ph, ty + th) - fminf(py, ty)), 0.0f);
                float inter = iw * ih;
                float uni = pw * ph + tw * th - inter;
                iou[b] = inter / (uni + 1e-10f);
            }
            const int resp = (iou[1] > iou[0]) ? 1 : 0;

            #pragma unroll
            for (int b = 0; b < 2; ++b) {
                const float ob = (b == resp) ? mask : 0.0f;
                const float* pb = P + 5 * b;
                const float* tb = T + 5 * b;
                float d0 = pb[0] - tb[0], d1 = pb[1] - tb[1];
                float d2 = pb[2] - tb[2], d3 = pb[3] - tb[3];
                acc += 5.0f * ob * (d0 * d0 + d1 * d1 + d2 * d2 + d3 * d3);
                float cf = pb[4];
                float dc = cf - iou[b];
                acc += ob * dc * dc + 0.5f * (1.0f - ob) * cf * cf;
            }
        } else {
            // ---- warps 2-3: class loss for cell (tid-64) ----
            const int ct = tid - TILE;
            const float* P = S + ct * NCH;
            const float* T = S + TILE * NCH + ct * NCH;
            const float mask = (T[9] > 0.0f) ? 1.0f : 0.0f;
            float cls = 0.0f;
            #pragma unroll
            for (int k = 10; k < 30; ++k) {
                float d = P[k] - T[k];
                cls += d * d;
            }
            acc += mask * cls;
        }
        // no trailing sync: next iteration's __syncthreads (after wait)
        // guards stage reuse.
    }

    // ---- single end-of-kernel block reduction ----
    #pragma unroll
    for (int o = 16; o; o >>= 1)
        acc += __shfl_down_sync(0xffffffffu, acc, o);
    if ((tid & 31) == 0) warpsum[tid >> 5] = acc;
    __syncthreads();

    if (tid == 0) {
        float s = (warpsum[0] + warpsum[1]) + (warpsum[2] + warpsum[3]);
        __stcg(&g_partials[bx], s);
        unsigned int rank;
        asm volatile("atom.acq_rel.gpu.global.add.u32 %0, [%1], %2;"
                     : "=r"(rank) : "l"(&g_count), "r"(1u) : "memory");
        s_rank = rank;
    }
    __syncthreads();

    // ---- last CTA folds all partials in fixed order ----
    if (s_rank == GRID - 1) {
        float s = 0.0f;
        for (int i = tid; i < GRID; i += THR)
            s += __ldcg(&g_partials[i]);
        #pragma unroll
        for (int o = 16; o; o >>= 1)
            s += __shfl_down_sync(0xffffffffu, s, o);
        __shared__ float fin[THR / 32];
        if ((tid & 31) == 0) fin[tid >> 5] = s;
        __syncthreads();
        if (tid == 0) {
            float tot = (fin[0] + fin[1]) + (fin[2] + fin[3]);
            out[0] = tot * invN;
            g_count = 0;                        // reset for graph replay
        }
    }
}

extern "C" void kernel_launch(void* const* d_in, const int* in_sizes, int n_in,
                              void* d_out, int out_size)
{
    const float* pred   = (const float*)d_in[0];
    const float* target = (const float*)d_in[1];
    const int total  = in_sizes[0];           // N*49*30
    const int ncells = total / NCH;           // 802816
    const int ntiles = ncells / TILE;         // 12544 (exact)
    const float invN = 1.0f / (float)(ncells / SCELL);

    yolo_loss_pipe<<<GRID, THR>>>(pred, target, ntiles, invN, (float*)d_out);
}